// round 11
// baseline (speedup 1.0000x reference)
#include <cuda_runtime.h>

// TransformDomainInterpolator, GB300 (sm_103a). Two-kernel split.
//
// Math: fc = M/2 keeps ALL 2048 DFT bins -> exact 2x bandlimited interp:
//   out[2m]   = x[m]
//   out[2m+1] = IDFT2048( DFT2048(x)[k] * w[k] )/2048,
//     w[k] = e^{+i*pi*k/2048} (k<1024), -e^{+i*pi*k/2048} (k>=1024)
// Time: out[t] = lerp(H2, H11, clamp((t-2)/9, 0, 1)).
//
// k1: one 256-thread block per (batch,row) FFT (1024 blocks -> ONE wave at
//     7 blocks/SM). Writes odd-values to __device__ scratch + the 3 output
//     symbols that depend only on its row (t=0..2 row0, t=11..13 row1).
// k2: pure streaming lerp for t=3..10 from pilots + scratch. No barriers.

#define MM 2048
#define NSYM 14
#define PADN 2176
#define PIDX(i) ((i) + ((i) >> 4))
#define C8v  0.70710678118654752f
#define CP8v 0.92387953251128676f
#define SP8v 0.38268343236508977f

__device__ float g_scratch[512 * 4096 * 2];   // 16MB: MODE0 uses 8MB as float

static __device__ __forceinline__ float2 cmul(float2 a, float2 b) {
    return make_float2(fmaf(a.x, b.x, -a.y * b.y), fmaf(a.x, b.y, a.y * b.x));
}
static __device__ __forceinline__ float2 cadd(float2 a, float2 b) {
    return make_float2(a.x + b.x, a.y + b.y);
}
static __device__ __forceinline__ float2 csub(float2 a, float2 b) {
    return make_float2(a.x - b.x, a.y - b.y);
}

// ---- radix-4 fused DIF stages (S+1, S)
template <int S>
static __device__ __forceinline__ void fwd4(float2* __restrict__ y,
                                            const float2* __restrict__ tw, int g)
{
    const int h1 = 1 << S;
    const int j  = g & (h1 - 1);
    const int i0 = ((g >> S) << (S + 2)) | j;
    float2 w  = tw[j << (9 - S)];
    float2 wm = make_float2(w.y, -w.x);
    float2 v  = tw[j << (10 - S)];
    float2 a = y[PIDX(i0)], bb = y[PIDX(i0 + h1)];
    float2 c = y[PIDX(i0 + 2 * h1)], d = y[PIDX(i0 + 3 * h1)];
    float2 a1 = cadd(a, c),  c1 = cmul(csub(a, c), w);
    float2 b1 = cadd(bb, d), d1 = cmul(csub(bb, d), wm);
    y[PIDX(i0)]          = cadd(a1, b1);
    y[PIDX(i0 + h1)]     = cmul(csub(a1, b1), v);
    y[PIDX(i0 + 2 * h1)] = cadd(c1, d1);
    y[PIDX(i0 + 3 * h1)] = cmul(csub(c1, d1), v);
}

// ---- radix-4 fused DIT stages (S, S+1), conjugate twiddles
template <int S>
static __device__ __forceinline__ void inv4(float2* __restrict__ y,
                                            const float2* __restrict__ tw, int g)
{
    const int h1 = 1 << S;
    const int j  = g & (h1 - 1);
    const int i0 = ((g >> S) << (S + 2)) | j;
    float2 w   = tw[j << (9 - S)];
    float2 cw  = make_float2(w.x, -w.y);
    float2 cw2 = make_float2(w.y, w.x);
    float2 v0  = tw[j << (10 - S)];
    float2 cv  = make_float2(v0.x, -v0.y);
    float2 a = y[PIDX(i0)], bb = y[PIDX(i0 + h1)];
    float2 c = y[PIDX(i0 + 2 * h1)], d = y[PIDX(i0 + 3 * h1)];
    float2 t  = cmul(bb, cv);
    float2 a1 = cadd(a, t), b1 = csub(a, t);
    t = cmul(d, cv);
    float2 c1 = cadd(c, t), d1 = csub(c, t);
    t = cmul(c1, cw);
    y[PIDX(i0)]          = cadd(a1, t);
    y[PIDX(i0 + 2 * h1)] = csub(a1, t);
    t = cmul(d1, cw2);
    y[PIDX(i0 + h1)]     = cadd(b1, t);
    y[PIDX(i0 + 3 * h1)] = csub(b1, t);
}

// ---- radix-8 fused DIF stages (S+2, S+1, S)
template <int S>
static __device__ __forceinline__ void fwd8(float2* __restrict__ y,
                                            const float2* __restrict__ tw, int q)
{
    const int h  = 1 << S;
    const int j  = q & (h - 1);
    const int i0 = ((q >> S) << (S + 3)) | j;
    float2 x[8];
    #pragma unroll
    for (int r = 0; r < 8; ++r) x[r] = y[PIDX(i0 + r * h)];
    #pragma unroll
    for (int r = 0; r < 4; ++r) {
        float2 wa = tw[(j + r * h) << (8 - S)];
        float2 u = x[r], v = x[r + 4];
        x[r] = cadd(u, v);
        x[r + 4] = cmul(csub(u, v), wa);
    }
    float2 wb0 = tw[j << (9 - S)];
    float2 wb1 = make_float2(wb0.y, -wb0.x);
    #pragma unroll
    for (int o = 0; o < 8; o += 4) {
        float2 u = x[o], v = x[o + 2];
        x[o] = cadd(u, v); x[o + 2] = cmul(csub(u, v), wb0);
        u = x[o + 1]; v = x[o + 3];
        x[o + 1] = cadd(u, v); x[o + 3] = cmul(csub(u, v), wb1);
    }
    float2 wc = tw[j << (10 - S)];
    #pragma unroll
    for (int g = 0; g < 4; ++g) {
        float2 u = x[2 * g], v = x[2 * g + 1];
        x[2 * g] = cadd(u, v); x[2 * g + 1] = cmul(csub(u, v), wc);
    }
    #pragma unroll
    for (int r = 0; r < 8; ++r) y[PIDX(i0 + r * h)] = x[r];
}

// ---- radix-8 fused DIT stages (S, S+1, S+2), conjugate twiddles
template <int S>
static __device__ __forceinline__ void inv8(float2* __restrict__ y,
                                            const float2* __restrict__ tw, int q)
{
    const int h  = 1 << S;
    const int j  = q & (h - 1);
    const int i0 = ((q >> S) << (S + 3)) | j;
    float2 x[8];
    #pragma unroll
    for (int r = 0; r < 8; ++r) x[r] = y[PIDX(i0 + r * h)];
    float2 wc0 = tw[j << (10 - S)];
    float2 wc  = make_float2(wc0.x, -wc0.y);
    #pragma unroll
    for (int g = 0; g < 4; ++g) {
        float2 v = cmul(x[2 * g + 1], wc);
        float2 u = x[2 * g];
        x[2 * g] = cadd(u, v); x[2 * g + 1] = csub(u, v);
    }
    float2 wb0  = tw[j << (9 - S)];
    float2 wb0c = make_float2(wb0.x, -wb0.y);
    float2 wb1c = make_float2(wb0.y, wb0.x);
    #pragma unroll
    for (int o = 0; o < 8; o += 4) {
        float2 v = cmul(x[o + 2], wb0c);
        float2 u = x[o];
        x[o] = cadd(u, v); x[o + 2] = csub(u, v);
        v = cmul(x[o + 3], wb1c);
        u = x[o + 1];
        x[o + 1] = cadd(u, v); x[o + 3] = csub(u, v);
    }
    #pragma unroll
    for (int r = 0; r < 4; ++r) {
        float2 wa0 = tw[(j + r * h) << (8 - S)];
        float2 wac = make_float2(wa0.x, -wa0.y);
        float2 v = cmul(x[r + 4], wac);
        float2 u = x[r];
        x[r] = cadd(u, v); x[r + 4] = csub(u, v);
    }
    #pragma unroll
    for (int r = 0; r < 8; ++r) y[PIDX(i0 + r * h)] = x[r];
}

// ============================ k1: per-row FFT ============================
// grid = 2*B blocks, 256 threads. block -> (batch = bid>>1, row = bid&1).
template <int MODE>
__global__ void __launch_bounds__(256, 7) tdi_fft_kernel(
    const float* __restrict__ re,
    const float* __restrict__ im,
    void* __restrict__ outv)
{
    __shared__ float2 tw[1024];
    __shared__ float2 ys[PADN];

    const int batch = blockIdx.x >> 1;
    const int row   = blockIdx.x & 1;
    const int q     = threadIdx.x;
    float2* __restrict__ y = ys;

    for (int t = q; t < 1024; t += 256) {
        float s, c;
        sincospif(-(float)t * (1.0f / 1024.0f), &s, &c);
        tw[t] = make_float2(c, s);
    }

    const float* rbr = re + (size_t)batch * 4096 + row * MM;
    const float* ibr = im + (size_t)batch * 4096 + row * MM;

    float2 x[8];
    #pragma unroll
    for (int r = 0; r < 8; ++r)
        x[r] = make_float2(rbr[q + 256 * r], ibr[q + 256 * r]);
    __syncthreads();                                  // tw ready

    // ---- P1: fwd stages 10,9,8 (h=256, j=q) from registers
    #pragma unroll
    for (int r = 0; r < 4; ++r) {
        float2 wa = tw[q + 256 * r];
        float2 u = x[r], v = x[r + 4];
        x[r] = cadd(u, v);
        x[r + 4] = cmul(csub(u, v), wa);
    }
    {
        float2 wb0 = tw[q << 1];
        float2 wb1 = make_float2(wb0.y, -wb0.x);
        #pragma unroll
        for (int o = 0; o < 8; o += 4) {
            float2 u = x[o], v = x[o + 2];
            x[o] = cadd(u, v); x[o + 2] = cmul(csub(u, v), wb0);
            u = x[o + 1]; v = x[o + 3];
            x[o + 1] = cadd(u, v); x[o + 3] = cmul(csub(u, v), wb1);
        }
        float2 wc = tw[q << 2];
        #pragma unroll
        for (int g = 0; g < 4; ++g) {
            float2 u = x[2 * g], v = x[2 * g + 1];
            x[2 * g] = cadd(u, v); x[2 * g + 1] = cmul(csub(u, v), wc);
        }
    }
    #pragma unroll
    for (int r = 0; r < 8; ++r) y[PIDX(q + 256 * r)] = x[r];
    __syncthreads();

    fwd8<5>(y, tw, q);                                // stages 7,6,5
    __syncthreads();
    fwd4<3>(y, tw, 2 * q); fwd4<3>(y, tw, 2 * q + 1); // stages 4,3
    __syncthreads();

    // ---- MID: fwd 2,1,0 + pointwise + inv 0,1,2 on 8 contiguous elems
    {
        const int p = 8 * q;
        #pragma unroll
        for (int r = 0; r < 8; ++r) x[r] = y[PIDX(p + r)];
        { float2 u=x[0], v=x[4]; x[0]=cadd(u,v); x[4]=csub(u,v); }
        { float2 u=x[1], v=x[5]; x[1]=cadd(u,v);
          x[5]=cmul(csub(u,v), make_float2(C8v,-C8v)); }
        { float2 u=x[2], v=x[6]; x[2]=cadd(u,v);
          float2 t=csub(u,v); x[6]=make_float2(t.y,-t.x); }
        { float2 u=x[3], v=x[7]; x[3]=cadd(u,v);
          x[7]=cmul(csub(u,v), make_float2(-C8v,-C8v)); }
        #pragma unroll
        for (int o = 0; o < 8; o += 4) {
            float2 u=x[o], v=x[o+2]; x[o]=cadd(u,v); x[o+2]=csub(u,v);
            u=x[o+1]; v=x[o+3]; x[o+1]=cadd(u,v);
            float2 t=csub(u,v); x[o+3]=make_float2(t.y,-t.x);
        }
        #pragma unroll
        for (int g = 0; g < 4; ++g) {
            float2 u=x[2*g], v=x[2*g+1];
            x[2*g]=cadd(u,v); x[2*g+1]=csub(u,v);
        }
        {
            const float K = 1.0f / 2048.0f;
            int kq = (int)(__brev((unsigned)q) >> 24);
            float sv, cv;
            sincospif((float)kq * (1.0f / 2048.0f), &sv, &cv);
            float2 base = make_float2(cv, sv);        // e^{+i*pi*kq/2048}
            const float2 S8[8] = {
                { K, 0.0f }, { 0.0f, -K },
                { K*C8v,  K*C8v }, { K*C8v, -K*C8v },
                { K*CP8v, K*SP8v }, { K*SP8v, -K*CP8v },
                { K*SP8v, K*CP8v }, { K*CP8v, -K*SP8v } };
            #pragma unroll
            for (int r = 0; r < 8; ++r) x[r] = cmul(x[r], cmul(base, S8[r]));
        }
        #pragma unroll
        for (int g = 0; g < 4; ++g) {
            float2 u=x[2*g], v=x[2*g+1];
            x[2*g]=cadd(u,v); x[2*g+1]=csub(u,v);
        }
        #pragma unroll
        for (int o = 0; o < 8; o += 4) {
            float2 u=x[o], v=x[o+2]; x[o]=cadd(u,v); x[o+2]=csub(u,v);
            u=x[o+1]; v=make_float2(-x[o+3].y, x[o+3].x);
            x[o+1]=cadd(u,v); x[o+3]=csub(u,v);
        }
        { float2 u=x[0], v=x[4]; x[0]=cadd(u,v); x[4]=csub(u,v); }
        { float2 u=x[1], v=cmul(x[5], make_float2(C8v,C8v));
          x[1]=cadd(u,v); x[5]=csub(u,v); }
        { float2 u=x[2], v=make_float2(-x[6].y, x[6].x);
          x[2]=cadd(u,v); x[6]=csub(u,v); }
        { float2 u=x[3], v=cmul(x[7], make_float2(-C8v,C8v));
          x[3]=cadd(u,v); x[7]=csub(u,v); }
        #pragma unroll
        for (int r = 0; r < 8; ++r) y[PIDX(p + r)] = x[r];
    }
    __syncthreads();

    inv4<3>(y, tw, 2 * q); inv4<3>(y, tw, 2 * q + 1); // stages 3,4
    __syncthreads();
    inv8<5>(y, tw, q);                                // stages 5,6,7
    __syncthreads();

    // ---- iP1: inv stages 8,9,10 -> ends in REGISTERS, natural m = q+256r.
    {
        #pragma unroll
        for (int r = 0; r < 8; ++r) x[r] = y[PIDX(q + 256 * r)];
        float2 wc0 = tw[q << 2];
        float2 wc  = make_float2(wc0.x, -wc0.y);
        #pragma unroll
        for (int g = 0; g < 4; ++g) {
            float2 v = cmul(x[2*g+1], wc);
            float2 u = x[2*g];
            x[2*g] = cadd(u, v); x[2*g+1] = csub(u, v);
        }
        float2 wb0  = tw[q << 1];
        float2 wb0c = make_float2(wb0.x, -wb0.y);
        float2 wb1c = make_float2(wb0.y, wb0.x);
        #pragma unroll
        for (int o = 0; o < 8; o += 4) {
            float2 v = cmul(x[o+2], wb0c);
            float2 u = x[o];
            x[o] = cadd(u, v); x[o+2] = csub(u, v);
            v = cmul(x[o+3], wb1c);
            u = x[o+1];
            x[o+1] = cadd(u, v); x[o+3] = csub(u, v);
        }
        #pragma unroll
        for (int r = 0; r < 4; ++r) {
            float2 wa0 = tw[q + 256 * r];
            float2 wac = make_float2(wa0.x, -wa0.y);
            float2 v = cmul(x[r+4], wac);
            float2 u = x[r];
            x[r] = cadd(u, v); x[r+4] = csub(u, v);
        }
    }

    // ---- Epilogue: scratch + the 3 row-exclusive output symbols.
    const int t0 = row ? 11 : 0;
    if (MODE == 0) {
        float* scr = g_scratch + ((size_t)batch * 2 + row) * MM;
        #pragma unroll
        for (int r = 0; r < 8; ++r) {
            int m = q + 256 * r;
            float d = x[r].x;
            float e = rbr[m];
            scr[m] = d;
            float2 v = make_float2(e, d);
            #pragma unroll
            for (int tt = 0; tt < 3; ++tt)
                ((float2*)outv)[((size_t)batch * NSYM + t0 + tt) * MM + m] = v;
        }
    } else {
        float2* scr = (float2*)g_scratch + ((size_t)batch * 2 + row) * MM;
        #pragma unroll
        for (int r = 0; r < 8; ++r) {
            int m = q + 256 * r;
            float2 d = x[r];
            float4 v = make_float4(rbr[m], ibr[m], d.x, d.y);
            scr[m] = d;
            #pragma unroll
            for (int tt = 0; tt < 3; ++tt)
                ((float4*)outv)[((size_t)batch * NSYM + t0 + tt) * MM + m] = v;
        }
    }
}

// ===================== k2: streaming lerp, t = 3..10 =====================
template <int MODE>
__global__ void __launch_bounds__(256) tdi_lerp_kernel(
    const float* __restrict__ re,
    const float* __restrict__ im,
    void* __restrict__ outv)
{
    const int b   = blockIdx.x;
    const int tid = threadIdx.x;
    const float* rb = re + (size_t)b * 4096;
    const float* ib = im + (size_t)b * 4096;

    #pragma unroll
    for (int s = 0; s < 8; ++s) {
        int m = tid + 256 * s;
        if (MODE == 0) {
            const float* scr = g_scratch + (size_t)b * 2 * MM;
            float e2  = rb[m],       e11 = rb[MM + m];
            float d2  = scr[m],      d11 = scr[MM + m];
            float de = e11 - e2, dd = d11 - d2;
            #pragma unroll
            for (int t = 3; t <= 10; ++t) {
                float a = (float)(t - 2) * (1.0f / 9.0f);
                float2 v = make_float2(fmaf(a, de, e2), fmaf(a, dd, d2));
                ((float2*)outv)[((size_t)b * NSYM + t) * MM + m] = v;
            }
        } else {
            const float2* scr = (const float2*)g_scratch + (size_t)b * 2 * MM;
            float2 e2  = make_float2(rb[m], ib[m]);
            float2 e11 = make_float2(rb[MM + m], ib[MM + m]);
            float2 d2  = scr[m], d11 = scr[MM + m];
            float2 de = csub(e11, e2), dd = csub(d11, d2);
            #pragma unroll
            for (int t = 3; t <= 10; ++t) {
                float a = (float)(t - 2) * (1.0f / 9.0f);
                float4 v = make_float4(fmaf(a, de.x, e2.x), fmaf(a, de.y, e2.y),
                                       fmaf(a, dd.x, d2.x), fmaf(a, dd.y, d2.y));
                ((float4*)outv)[((size_t)b * NSYM + t) * MM + m] = v;
            }
        }
    }
}

extern "C" void kernel_launch(void* const* d_in, const int* in_sizes, int n_in,
                              void* d_out, int out_size)
{
    const float* re = (const float*)d_in[0];
    const float* im = (const float*)d_in[1];
    const int B = in_sizes[0] / 4096;
    const long long interleaved = (long long)B * NSYM * 4096 * 2;

    if ((long long)out_size >= interleaved) {
        tdi_fft_kernel<1><<<2 * B, 256>>>(re, im, d_out);
        tdi_lerp_kernel<1><<<B, 256>>>(re, im, d_out);
    } else {
        tdi_fft_kernel<0><<<2 * B, 256>>>(re, im, d_out);
        tdi_lerp_kernel<0><<<B, 256>>>(re, im, d_out);
    }
}